// round 3
// baseline (speedup 1.0000x reference)
#include <cuda_runtime.h>
#include <cuda_bf16.h>
#include <cstdint>

// Problem constants (fixed by the reference)
#define NNODES 50000
#define NEDGES 600000
#define FDIM   128

// Scratch: aggregated neighbor features x_j [N, F]. __device__ global (no alloc).
__device__ float g_xj[NNODES * FDIM];
// Flag: 1 if edge_index is int64, 0 if int32 (JAX default demotes to int32).
__device__ int g_ei_is_i64;

// ---------------------------------------------------------------------------
// Kernel 0: probe edge_index dtype. If the buffer really is int64, every
// value is a valid node id in [0, N). If it's int32 reinterpreted as int64,
// values are ~hi*2^32+lo -> out of range with overwhelming probability.
// ---------------------------------------------------------------------------
__global__ void probe_ei_kernel(const void* ei) {
    if (threadIdx.x == 0 && blockIdx.x == 0) {
        const long long* p = (const long long*)ei;
        int ok = 1;
#pragma unroll
        for (int i = 0; i < 16; i++) {
            long long v = p[i];
            if (v < 0 || v >= NNODES) ok = 0;
        }
        g_ei_is_i64 = ok;
    }
}

// ---------------------------------------------------------------------------
// Kernel 1: zero the scratch accumulator (every launch; graph replays).
// ---------------------------------------------------------------------------
__global__ void zero_xj_kernel() {
    const int total4 = NNODES * FDIM / 4;  // float4 count
    int idx = blockIdx.x * blockDim.x + threadIdx.x;
    if (idx < total4) {
        reinterpret_cast<float4*>(g_xj)[idx] = make_float4(0.f, 0.f, 0.f, 0.f);
    }
}

// ---------------------------------------------------------------------------
// Kernel 2: scatter-add. One warp per edge. Lane l moves floats [4l, 4l+4)
// of row x[src] into g_xj[dst] via vectorized red.global.add.v4.f32.
// Lanes 0 and 1 fetch src/dst indices in parallel.
// ---------------------------------------------------------------------------
__global__ void scatter_kernel(const float* __restrict__ x,
                               const void* __restrict__ edge_index) {
    int warp_in_block = threadIdx.x >> 5;
    int lane = threadIdx.x & 31;
    int e = blockIdx.x * (blockDim.x >> 5) + warp_in_block;
    if (e >= NEDGES) return;

    int v01 = 0;
    if (lane < 2) {
        long long ofs = (long long)lane * NEDGES + e;
        if (g_ei_is_i64) {
            v01 = (int)((const long long*)edge_index)[ofs];
        } else {
            v01 = ((const int*)edge_index)[ofs];
        }
    }
    int s = __shfl_sync(0xFFFFFFFFu, v01, 0);
    int d = __shfl_sync(0xFFFFFFFFu, v01, 1);

    const float4 v = *reinterpret_cast<const float4*>(&x[(long long)s * FDIM + lane * 4]);
    float* dst = &g_xj[(long long)d * FDIM + lane * 4];
    asm volatile("red.global.add.v4.f32 [%0], {%1, %2, %3, %4};"
                 :: "l"(dst), "f"(v.x), "f"(v.y), "f"(v.z), "f"(v.w)
                 : "memory");
}

// ---------------------------------------------------------------------------
// Kernel 3: C[N,128] = A[N,128] @ B[128,128] + bias.
// Block tile: 128 rows x 128 cols, 256 threads, 8x8 outputs/thread,
// K-chunks of 16 through shared memory.
// ---------------------------------------------------------------------------
__global__ __launch_bounds__(256, 2)
void gemm_kernel(const float* __restrict__ A,
                 const float* __restrict__ B,
                 const float* __restrict__ bias,
                 float* __restrict__ C,
                 int nrows) {
    __shared__ float As[128][16];
    __shared__ float Bs[16][128];

    const int tid = threadIdx.x;          // 0..255
    const int rg  = tid >> 4;             // 0..15 (row group of 8)
    const int cg  = tid & 15;             // 0..15 (col group of 8)
    const int row0 = blockIdx.x * 128;

    float acc[8][8];
#pragma unroll
    for (int i = 0; i < 8; i++)
#pragma unroll
        for (int j = 0; j < 8; j++) acc[i][j] = 0.f;

    for (int kc = 0; kc < FDIM; kc += 16) {
#pragma unroll
        for (int i = 0; i < 2; i++) {
            int idx = tid + i * 256;
            int r = idx >> 2, k4 = idx & 3;
            float4 v = make_float4(0.f, 0.f, 0.f, 0.f);
            if (row0 + r < nrows)
                v = *reinterpret_cast<const float4*>(&A[(long long)(row0 + r) * FDIM + kc + k4 * 4]);
            *reinterpret_cast<float4*>(&As[r][k4 * 4]) = v;
        }
#pragma unroll
        for (int i = 0; i < 2; i++) {
            int idx = tid + i * 256;
            int k = idx >> 5, c4 = idx & 31;
            *reinterpret_cast<float4*>(&Bs[k][c4 * 4]) =
                *reinterpret_cast<const float4*>(&B[(kc + k) * FDIM + c4 * 4]);
        }
        __syncthreads();

#pragma unroll
        for (int k = 0; k < 16; k++) {
            float a[8], b[8];
#pragma unroll
            for (int i = 0; i < 8; i++) a[i] = As[rg * 8 + i][k];
#pragma unroll
            for (int j = 0; j < 8; j++) b[j] = Bs[k][cg * 8 + j];
#pragma unroll
            for (int i = 0; i < 8; i++)
#pragma unroll
                for (int j = 0; j < 8; j++) acc[i][j] += a[i] * b[j];
        }
        __syncthreads();
    }

    float bia[8];
#pragma unroll
    for (int j = 0; j < 8; j++) bia[j] = bias[cg * 8 + j];

#pragma unroll
    for (int i = 0; i < 8; i++) {
        int r = row0 + rg * 8 + i;
        if (r < nrows) {
            float4 o0, o1;
            o0.x = acc[i][0] + bia[0]; o0.y = acc[i][1] + bia[1];
            o0.z = acc[i][2] + bia[2]; o0.w = acc[i][3] + bia[3];
            o1.x = acc[i][4] + bia[4]; o1.y = acc[i][5] + bia[5];
            o1.z = acc[i][6] + bia[6]; o1.w = acc[i][7] + bia[7];
            float4* out = reinterpret_cast<float4*>(&C[(long long)r * FDIM + cg * 8]);
            out[0] = o0;
            out[1] = o1;
        }
    }
}

// ---------------------------------------------------------------------------
// kernel_launch
// Inputs (metadata order): 0:x [N*128] f32, 1:edge_index [2*E] (i32 or i64),
// 2:edge_weight (unused), 3:W1 (unused), 4:b1 (unused),
// 5:W2 [128*128] f32, 6:b2 [128] f32, 7:a (unused), 8:b (unused)
// Output: wh_2 [N*128] f32
// ---------------------------------------------------------------------------
extern "C" void kernel_launch(void* const* d_in, const int* in_sizes, int n_in,
                              void* d_out, int out_size) {
    const float* x   = (const float*)d_in[0];
    const void*  ei  = d_in[1];
    const float* W2  = (const float*)d_in[5];
    const float* b2  = (const float*)d_in[6];
    float*       out = (float*)d_out;

    float* xj = nullptr;
    cudaGetSymbolAddress((void**)&xj, g_xj);

    // 0) probe edge_index dtype
    probe_ei_kernel<<<1, 32>>>(ei);

    // 1) zero scratch
    {
        int total4 = NNODES * FDIM / 4;
        int threads = 256;
        int blocks = (total4 + threads - 1) / threads;
        zero_xj_kernel<<<blocks, threads>>>();
    }
    // 2) scatter-add (warp per edge, 8 warps per block)
    {
        int threads = 256;
        int warps_per_block = threads / 32;
        int blocks = (NEDGES + warps_per_block - 1) / warps_per_block;
        scatter_kernel<<<blocks, threads>>>(x, ei);
    }
    // 3) GEMM + bias
    {
        int blocks = (NNODES + 127) / 128;
        gemm_kernel<<<blocks, 256>>>(xj, W2, b2, out, NNODES);
    }
}

// round 5
// speedup vs baseline: 1.1092x; 1.1092x over previous
#include <cuda_runtime.h>
#include <cuda_bf16.h>
#include <cstdint>

#define NNODES 50000
#define NEDGES 600000
#define FDIM   128
#define NSCAN_BLOCKS 49   // ceil(50000/1024)

// ---------------------------------------------------------------------------
// Device scratch (no allocations allowed)
// ---------------------------------------------------------------------------
__device__ float g_xj[NNODES * FDIM];        // aggregated neighbor features
__device__ int   g_cnt[NNODES];              // per-dst degree
__device__ int   g_off[NNODES + 1];          // CSR offsets
__device__ int   g_fill[NNODES];             // running fill pointers
__device__ int   g_srcs[NEDGES];             // src ids sorted by dst
__device__ int   g_bsum[NSCAN_BLOCKS];       // scan partials
__device__ int   g_boff[NSCAN_BLOCKS];
__device__ int   g_ei_is_i64;                // edge_index dtype flag
__device__ __nv_bfloat16 g_w2hi[FDIM * FDIM]; // W2^T hi, layout [n][k]
__device__ __nv_bfloat16 g_w2lo[FDIM * FDIM]; // W2^T lo, layout [n][k]

// ---------------------------------------------------------------------------
// Kernel: probe edge_index dtype. Real int64 values are all in [0,N);
// int32 reinterpreted as int64 lands out of range with overwhelming prob.
// ---------------------------------------------------------------------------
__global__ void probe_ei_kernel(const void* ei) {
    if (threadIdx.x == 0 && blockIdx.x == 0) {
        const long long* p = (const long long*)ei;
        int ok = 1;
#pragma unroll
        for (int i = 0; i < 16; i++) {
            long long v = p[i];
            if (v < 0 || v >= NNODES) ok = 0;
        }
        g_ei_is_i64 = ok;
    }
}

// ---------------------------------------------------------------------------
// CSR build: zero counters, histogram, 2-level scan, fixup, reorder
// ---------------------------------------------------------------------------
__global__ void init_cnt_kernel() {
    int i = blockIdx.x * blockDim.x + threadIdx.x;
    if (i < NNODES) g_cnt[i] = 0;
}

__global__ void hist_kernel(const void* __restrict__ ei) {
    int e = blockIdx.x * blockDim.x + threadIdx.x;
    if (e >= NEDGES) return;
    int d = g_ei_is_i64 ? (int)((const long long*)ei)[NEDGES + e]
                        : ((const int*)ei)[NEDGES + e];
    atomicAdd(&g_cnt[d], 1);
}

__global__ void scan1_kernel() {  // 49 blocks x 1024
    int tid = threadIdx.x;
    int i = blockIdx.x * 1024 + tid;
    int v = (i < NNODES) ? g_cnt[i] : 0;
    int incl = v;
#pragma unroll
    for (int o = 1; o < 32; o <<= 1) {
        int n = __shfl_up_sync(0xFFFFFFFFu, incl, o);
        if ((tid & 31) >= o) incl += n;
    }
    __shared__ int ws[32];
    if ((tid & 31) == 31) ws[tid >> 5] = incl;
    __syncthreads();
    if (tid < 32) {
        int w = ws[tid];
        int wincl = w;
#pragma unroll
        for (int o = 1; o < 32; o <<= 1) {
            int n = __shfl_up_sync(0xFFFFFFFFu, wincl, o);
            if (tid >= o) wincl += n;
        }
        ws[tid] = wincl - w;
        if (tid == 31) g_bsum[blockIdx.x] = wincl;
    }
    __syncthreads();
    int excl = incl - v + ws[tid >> 5];
    if (i < NNODES) g_off[i] = excl;
}

__global__ void scan2_kernel() {  // 1 block x 64
    int tid = threadIdx.x;
    int v = (tid < NSCAN_BLOCKS) ? g_bsum[tid] : 0;
    int incl = v;
#pragma unroll
    for (int o = 1; o < 32; o <<= 1) {
        int n = __shfl_up_sync(0xFFFFFFFFu, incl, o);
        if ((tid & 31) >= o) incl += n;
    }
    __shared__ int w0tot;
    if (tid == 31) w0tot = incl;
    __syncthreads();
    int excl = incl - v + ((tid >= 32) ? w0tot : 0);
    if (tid < NSCAN_BLOCKS) g_boff[tid] = excl;
}

__global__ void fixup_kernel() {
    int i = blockIdx.x * blockDim.x + threadIdx.x;
    if (i < NNODES) {
        int o = g_off[i] + g_boff[i >> 10];
        g_off[i] = o;
        g_fill[i] = o;
    }
    if (i == 0) g_off[NNODES] = NEDGES;
}

__global__ void reorder_kernel(const void* __restrict__ ei) {
    int e = blockIdx.x * blockDim.x + threadIdx.x;
    if (e >= NEDGES) return;
    int s, d;
    if (g_ei_is_i64) {
        const long long* p = (const long long*)ei;
        s = (int)p[e];
        d = (int)p[NEDGES + e];
    } else {
        const int* p = (const int*)ei;
        s = p[e];
        d = p[NEDGES + e];
    }
    int pos = atomicAdd(&g_fill[d], 1);
    g_srcs[pos] = s;
}

// ---------------------------------------------------------------------------
// Aggregate: one warp per node, accumulate gathered rows, write once.
// ---------------------------------------------------------------------------
__global__ void aggregate_kernel(const float* __restrict__ x) {
    int gw = (blockIdx.x * blockDim.x + threadIdx.x) >> 5;
    int lane = threadIdx.x & 31;
    if (gw >= NNODES) return;
    int beg = g_off[gw], end = g_off[gw + 1];
    float4 acc = make_float4(0.f, 0.f, 0.f, 0.f);
    int i = beg;
    for (; i + 1 < end; i += 2) {
        int s0 = g_srcs[i], s1 = g_srcs[i + 1];
        float4 v0 = *reinterpret_cast<const float4*>(&x[(size_t)s0 * FDIM + lane * 4]);
        float4 v1 = *reinterpret_cast<const float4*>(&x[(size_t)s1 * FDIM + lane * 4]);
        acc.x += v0.x + v1.x; acc.y += v0.y + v1.y;
        acc.z += v0.z + v1.z; acc.w += v0.w + v1.w;
    }
    if (i < end) {
        int s0 = g_srcs[i];
        float4 v0 = *reinterpret_cast<const float4*>(&x[(size_t)s0 * FDIM + lane * 4]);
        acc.x += v0.x; acc.y += v0.y; acc.z += v0.z; acc.w += v0.w;
    }
    *reinterpret_cast<float4*>(&g_xj[(size_t)gw * FDIM + lane * 4]) = acc;
}

// ---------------------------------------------------------------------------
// W2 prep: transpose to [n][k] and split fp32 -> bf16 hi + lo.
// ---------------------------------------------------------------------------
__global__ void w2_prep_kernel(const float* __restrict__ W2) {
    int idx = blockIdx.x * blockDim.x + threadIdx.x;
    if (idx < FDIM * FDIM) {
        int k = idx >> 7, n = idx & 127;
        float f = W2[idx];
        __nv_bfloat16 h = __float2bfloat16(f);
        float l = f - __bfloat162float(h);
        g_w2hi[n * FDIM + k] = h;
        g_w2lo[n * FDIM + k] = __float2bfloat16(l);
    }
}

// ---------------------------------------------------------------------------
// Tensor-core GEMM via mma.sync (bf16x3): C = A @ W2 + bias.
// 256 threads / 8 warps; warp computes 16 rows x 128 cols, K=128.
// A fragments from direct coalesced f32 loads (each element read once).
// B fragments from L1-resident transposed hi/lo tables.
// ---------------------------------------------------------------------------
__device__ __forceinline__ void mma_bf16(float* c, uint32_t a0, uint32_t a1,
                                         uint32_t a2, uint32_t a3,
                                         uint32_t b0, uint32_t b1) {
    asm volatile(
        "mma.sync.aligned.m16n8k16.row.col.f32.bf16.bf16.f32 "
        "{%0,%1,%2,%3}, {%4,%5,%6,%7}, {%8,%9}, {%0,%1,%2,%3};"
        : "+f"(c[0]), "+f"(c[1]), "+f"(c[2]), "+f"(c[3])
        : "r"(a0), "r"(a1), "r"(a2), "r"(a3), "r"(b0), "r"(b1));
}

__device__ __forceinline__ uint32_t pack_hi(float2 f) {
    __nv_bfloat162 h = __floats2bfloat162_rn(f.x, f.y);
    return *reinterpret_cast<uint32_t*>(&h);
}
__device__ __forceinline__ uint32_t pack_lo(float2 f) {
    float lx = f.x - __bfloat162float(__float2bfloat16(f.x));
    float ly = f.y - __bfloat162float(__float2bfloat16(f.y));
    __nv_bfloat162 h = __floats2bfloat162_rn(lx, ly);
    return *reinterpret_cast<uint32_t*>(&h);
}

__global__ __launch_bounds__(256)
void mma_gemm_kernel(const float* __restrict__ A,
                     const float* __restrict__ bias,
                     float* __restrict__ C,
                     int nrows) {
    const int lane = threadIdx.x & 31;
    const int wid  = threadIdx.x >> 5;
    const int g = lane >> 2;      // 0..7
    const int t = lane & 3;       // 0..3
    const int row0 = blockIdx.x * 128 + wid * 16;
    const int r0 = row0 + g;
    const int r1 = row0 + g + 8;

    float acc[16][4];
#pragma unroll
    for (int nt = 0; nt < 16; nt++)
#pragma unroll
        for (int j = 0; j < 4; j++) acc[nt][j] = 0.f;

    const float2 z2 = make_float2(0.f, 0.f);

#pragma unroll 1
    for (int kt = 0; kt < 8; kt++) {
        const int k0 = kt * 16;
        // A fragment elements (row-major m16k16): f32 loads, convert hi/lo.
        float2 f0 = z2, f1 = z2, f2 = z2, f3 = z2;
        if (r0 < nrows) {
            f0 = *reinterpret_cast<const float2*>(&A[(size_t)r0 * FDIM + k0 + 2 * t]);
            f2 = *reinterpret_cast<const float2*>(&A[(size_t)r0 * FDIM + k0 + 2 * t + 8]);
        }
        if (r1 < nrows) {
            f1 = *reinterpret_cast<const float2*>(&A[(size_t)r1 * FDIM + k0 + 2 * t]);
            f3 = *reinterpret_cast<const float2*>(&A[(size_t)r1 * FDIM + k0 + 2 * t + 8]);
        }
        uint32_t ah0 = pack_hi(f0), ah1 = pack_hi(f1), ah2 = pack_hi(f2), ah3 = pack_hi(f3);
        uint32_t al0 = pack_lo(f0), al1 = pack_lo(f1), al2 = pack_lo(f2), al3 = pack_lo(f3);

#pragma unroll
        for (int nt = 0; nt < 16; nt++) {
            const int nrow = nt * 8 + g;          // B^T row (= output col group)
            const int kcol = k0 + 2 * t;
            uint32_t bh0 = *reinterpret_cast<const uint32_t*>(&g_w2hi[nrow * FDIM + kcol]);
            uint32_t bh1 = *reinterpret_cast<const uint32_t*>(&g_w2hi[nrow * FDIM + kcol + 8]);
            uint32_t bl0 = *reinterpret_cast<const uint32_t*>(&g_w2lo[nrow * FDIM + kcol]);
            uint32_t bl1 = *reinterpret_cast<const uint32_t*>(&g_w2lo[nrow * FDIM + kcol + 8]);
            mma_bf16(acc[nt], ah0, ah1, ah2, ah3, bh0, bh1);
            mma_bf16(acc[nt], ah0, ah1, ah2, ah3, bl0, bl1);
            mma_bf16(acc[nt], al0, al1, al2, al3, bh0, bh1);
        }
    }

    // Epilogue: c0,c1 -> (r0, n0+2t..+1); c2,c3 -> (r1, same cols)
#pragma unroll
    for (int nt = 0; nt < 16; nt++) {
        const int c = nt * 8 + 2 * t;
        float bx = __ldg(&bias[c]);
        float by = __ldg(&bias[c + 1]);
        if (r0 < nrows) {
            float2 o = make_float2(acc[nt][0] + bx, acc[nt][1] + by);
            *reinterpret_cast<float2*>(&C[(size_t)r0 * FDIM + c]) = o;
        }
        if (r1 < nrows) {
            float2 o = make_float2(acc[nt][2] + bx, acc[nt][3] + by);
            *reinterpret_cast<float2*>(&C[(size_t)r1 * FDIM + c]) = o;
        }
    }
}

// ---------------------------------------------------------------------------
// kernel_launch
// Inputs: 0:x, 1:edge_index, 2:edge_weight(u), 3:W1(u), 4:b1(u),
//         5:W2, 6:b2, 7:a(u), 8:b(u).  Output: [N,128] f32
// ---------------------------------------------------------------------------
extern "C" void kernel_launch(void* const* d_in, const int* in_sizes, int n_in,
                              void* d_out, int out_size) {
    const float* x   = (const float*)d_in[0];
    const void*  ei  = d_in[1];
    const float* W2  = (const float*)d_in[5];
    const float* b2  = (const float*)d_in[6];
    float*       out = (float*)d_out;

    float* xj = nullptr;
    cudaGetSymbolAddress((void**)&xj, g_xj);

    probe_ei_kernel<<<1, 32>>>(ei);
    w2_prep_kernel<<<(FDIM * FDIM + 255) / 256, 256>>>(W2);
    init_cnt_kernel<<<(NNODES + 1023) / 1024, 1024>>>();
    hist_kernel<<<(NEDGES + 255) / 256, 256>>>(ei);
    scan1_kernel<<<NSCAN_BLOCKS, 1024>>>();
    scan2_kernel<<<1, 64>>>();
    fixup_kernel<<<(NNODES + 1023) / 1024, 1024>>>();
    reorder_kernel<<<(NEDGES + 255) / 256, 256>>>(ei);
    aggregate_kernel<<<(NNODES * 32 + 255) / 256, 256>>>(x);
    mma_gemm_kernel<<<(NNODES + 127) / 128, 256>>>(xj, b2, out, NNODES);
}